// round 8
// baseline (speedup 1.0000x reference)
#include <cuda_runtime.h>
#include <cstdint>

#define NN 32768
#define KK 4000
#define DD 128
#define CC 1000

#define BM 128
#define BN 128
#define NTILES 32
#define KPAD 4096
#define TM 8
#define TN 8
#define NTHREADS 256

#define QSCALE 31.75f                      // 127/4; clamp at +-4 sigma
#define DEQ2 (1.0f/(QSCALE*QSCALE))        // dequant factor for dotint
#define WMARG 6.0f                         // candidate window >> 2*max score err
#define CAP 16

// ---------------- global scratch (static, no allocs) ----------------
__device__ float g_x2[NN];
__device__ float g_p2[KPAD];
__device__ int   g_idx[NN];
// quantized, pre-arranged for verbatim cp.async tiles:
// g_xq[tile][g][row] / g_pq[tile][g][k], g = d/4 group, 4 int8 packed per word
__device__ __align__(16) uint32_t g_xq[NN * 32];     // 4MB
__device__ __align__(16) uint32_t g_pq[KPAD * 32];   // 512KB
__device__ int g_candn[NN];
__device__ int g_candk[NN * CAP];

// ---------------- asm helpers ----------------
__device__ __forceinline__ int dp4a(uint32_t a, uint32_t b, int c) {
    int d;
    asm("dp4a.s32.s32 %0, %1, %2, %3;" : "=r"(d) : "r"(a), "r"(b), "r"(c));
    return d;
}
__device__ __forceinline__ uint32_t smem_u32(const void* p) {
    uint32_t a;
    asm("{ .reg .u64 t; cvta.to.shared.u64 t, %1; cvt.u32.u64 %0, t; }" : "=r"(a) : "l"(p));
    return a;
}
__device__ __forceinline__ void cpa16(uint32_t dst, const void* src) {
    asm volatile("cp.async.cg.shared.global [%0], [%1], 16;" :: "r"(dst), "l"(src));
}
#define CP_COMMIT() asm volatile("cp.async.commit_group;")
#define CP_WAIT(n)  asm volatile("cp.async.wait_group %0;" :: "n"(n))

__device__ __forceinline__ int q1(float v) {
    return __float2int_rn(fminf(fmaxf(v, -4.f), 4.f) * QSCALE);
}
__device__ __forceinline__ uint32_t quant4(float4 v) {
    int a = q1(v.x), b = q1(v.y), c = q1(v.z), d = q1(v.w);
    return (uint32_t)(a & 0xff) | ((uint32_t)(b & 0xff) << 8) |
           ((uint32_t)(c & 0xff) << 16) | ((uint32_t)(d & 0xff) << 24);
}

// ---------------- quantize + rearrange ----------------
__global__ void quant_x_kernel(const float* __restrict__ x) {
    int c = blockIdx.x * 256 + threadIdx.x;        // NN*32
    int tile = c >> 12, g = (c >> 7) & 31, row = c & 127;
    float4 v = *(const float4*)(x + ((size_t)(tile * 128 + row)) * DD + g * 4);
    g_xq[((size_t)tile * 32 + g) * 128 + row] = quant4(v);
}

__global__ void quant_p_kernel(const float* __restrict__ p) {
    int c = blockIdx.x * 256 + threadIdx.x;        // KPAD*32
    int tile = c >> 12, g = (c >> 7) & 31, kk = c & 127;
    int k = tile * 128 + kk;
    uint32_t qv = 0;
    if (k < KK) {
        float4 v = *(const float4*)(p + (size_t)k * DD + g * 4);
        qv = quant4(v);
    } else if (g == 0) {
        g_p2[k] = 3.0e38f;     // pad sentinel: never wins, never a candidate
    }
    g_pq[((size_t)tile * 32 + g) * 128 + kk] = qv;
}

// ---------------- row squared norms (exact fp32) ----------------
__global__ void row_norm_kernel(const float* __restrict__ A, float* __restrict__ out, int rows) {
    int row  = blockIdx.x * 8 + (threadIdx.x >> 5);
    int lane = threadIdx.x & 31;
    if (row >= rows) return;
    const float* a = A + (size_t)row * DD;
    float s = 0.f;
#pragma unroll
    for (int i = 0; i < DD / 32; i++) { float v = a[lane + 32 * i]; s = fmaf(v, v, s); }
#pragma unroll
    for (int o = 16; o > 0; o >>= 1) s += __shfl_down_sync(0xffffffffu, s, o);
    if (lane == 0) out[row] = s;
}

// ---------------- smem layout (uint32 words) ----------------
#define IQ_A  0                  // 4096 words (16KB)
#define IQ_B  4096               // 2 x 4096 words
#define IQ_P2 12288              // 2 x 128 floats
#define SMEM_WORDS 12544
#define SMEM_BYTES (SMEM_WORDS * 4)

extern __shared__ uint32_t smq[];

// ---------------- int8 score GEMM + packed argmin + candidate window ----------
__global__ __launch_bounds__(NTHREADS, 2)
void argmin_i8_kernel() {
    uint32_t sb  = smem_u32(smq);
    uint32_t* As = smq + IQ_A;
    float*   p2s = (float*)(smq + IQ_P2);

    int tid = threadIdx.x;
    int tx  = tid & 15;      // k-group  (TN=8)
    int ty  = tid >> 4;      // row-group (TM=8)
    int rowBase = blockIdx.x * BM;

    // prologue: A tile + B tile0 (group 0), B tile1 (group 1) — verbatim copies
    {
        const char* srcA = (const char*)(g_xq + (size_t)blockIdx.x * 4096);
#pragma unroll
        for (int j = 0; j < 4; j++) cpa16(sb + IQ_A * 4 + (tid + 256 * j) * 16, srcA + (tid + 256 * j) * 16);
        const char* srcB = (const char*)(g_pq);
#pragma unroll
        for (int j = 0; j < 4; j++) cpa16(sb + IQ_B * 4 + (tid + 256 * j) * 16, srcB + (tid + 256 * j) * 16);
        if (tid < BN) p2s[tid] = g_p2[tid];
        CP_COMMIT();
        const char* srcB1 = (const char*)(g_pq + 4096);
#pragma unroll
        for (int j = 0; j < 4; j++) cpa16(sb + (IQ_B + 4096) * 4 + (tid + 256 * j) * 16, srcB1 + (tid + 256 * j) * 16);
        if (tid < BN) p2s[BN + tid] = g_p2[BN + tid];
        CP_COMMIT();
    }

    float x2r[TM];
#pragma unroll
    for (int i = 0; i < TM; i++) x2r[i] = g_x2[rowBase + ty * TM + i];

    int best[TM];                 // packed: (score_bits & ~0xFFF) | k   (scores > 0)
#pragma unroll
    for (int i = 0; i < TM; i++) best[i] = 0x7fffffff;
    int res[3]; int rcnt = 0;     // shared candidate slots: (i<<12)|k

    for (int t = 0; t < NTILES; t++) {
        int b = t & 1;
        if (t == NTILES - 1) { CP_WAIT(0); } else { CP_WAIT(1); }
        __syncthreads();

        int acc[TM][TN];
#pragma unroll
        for (int i = 0; i < TM; i++)
#pragma unroll
            for (int j = 0; j < TN; j++) acc[i][j] = 0;

        const uint32_t* Bs = smq + IQ_B + b * 4096;
#pragma unroll 4
        for (int g = 0; g < 32; g++) {
            uint4 xa0 = *(const uint4*)(As + g * 128 + ty * TM);
            uint4 xa1 = *(const uint4*)(As + g * 128 + ty * TM + 4);
            uint4 pb0 = *(const uint4*)(Bs + g * 128 + tx * TN);
            uint4 pb1 = *(const uint4*)(Bs + g * 128 + tx * TN + 4);
            uint32_t xs[TM] = {xa0.x, xa0.y, xa0.z, xa0.w, xa1.x, xa1.y, xa1.z, xa1.w};
            uint32_t ps[TN] = {pb0.x, pb0.y, pb0.z, pb0.w, pb1.x, pb1.y, pb1.z, pb1.w};
#pragma unroll
            for (int i = 0; i < TM; i++)
#pragma unroll
                for (int j = 0; j < TN; j++)
                    acc[i][j] = dp4a(xs[i], ps[j], acc[i][j]);
        }

        // epilogue: approx scores, packed argmin, candidate-window pushes
        const float* pp = p2s + b * BN + tx * TN;
        int ktb = t * BN + tx * TN;
#pragma unroll
        for (int j = 0; j < TN; j++) {
            float p2v = pp[j];
            int kg = ktb + j;
#pragma unroll
            for (int i = 0; i < TM; i++) {
                float s = fmaf(-2.0f * DEQ2, (float)acc[i][j], x2r[i] + p2v);
                int pk = (__float_as_int(s) & 0xFFFFF000) | kg;
                int ob = best[i];
                float obf = __int_as_float(ob & 0xFFFFF000);
                if (pk < ob) {
                    best[i] = pk;
                    if (obf <= s + WMARG) {                       // displaced near-tie
                        if (rcnt < 3) res[rcnt] = (i << 12) | (ob & 0xFFF);
                        rcnt++;
                    }
                } else if (s <= obf + WMARG) {                    // near-tie, not best
                    if (rcnt < 3) res[rcnt] = (i << 12) | kg;
                    rcnt++;
                }
            }
        }
        __syncthreads();

        if (t + 2 < NTILES) {      // refill buffer b with tile t+2
            const char* src = (const char*)(g_pq + (size_t)(t + 2) * 4096);
            uint32_t dst = sb + (IQ_B + b * 4096) * 4;
#pragma unroll
            for (int j = 0; j < 4; j++) cpa16(dst + (tid + 256 * j) * 16, src + (tid + 256 * j) * 16);
            if (tid < BN) p2s[b * BN + tid] = g_p2[(t + 2) * BN + tid];
            CP_COMMIT();
        }
    }

    // ---- cross-thread reduction: integer min of packed (score|k), 16 per row ----
    int* red = (int*)(smq + IQ_B);            // [16][128]
    int* big = (int*)(smq + IQ_B + 2048);     // [128] packed global best
#pragma unroll
    for (int i = 0; i < TM; i++) red[tx * BM + ty * TM + i] = best[i];
    __syncthreads();
    if (tid < BM) {
        int m = 0x7fffffff;
#pragma unroll
        for (int j = 0; j < 16; j++) m = min(m, red[j * BM + tid]);
        g_idx[rowBase + tid] = m & 0xFFF;
        big[tid] = m;
    }
    __syncthreads();

    // ---- candidate append for exact fixup ----
    if (rcnt > 3) {                             // thread overflow -> full scan rows
#pragma unroll
        for (int i = 0; i < TM; i++) atomicAdd(&g_candn[rowBase + ty * TM + i], 1 << 20);
    } else {
        for (int j = 0; j < rcnt; j++) {
            int e = res[j], i = e >> 12, k = e & 0xFFF;
            int rl = ty * TM + i;
            if (k != (big[rl] & 0xFFF)) {
                int pos = atomicAdd(&g_candn[rowBase + rl], 1);
                if (pos < CAP) g_candk[(rowBase + rl) * CAP + pos] = k;
            }
        }
#pragma unroll
        for (int i = 0; i < TM; i++) {
            int rl = ty * TM + i;
            int gb = big[rl], mk = best[i] & 0xFFF;
            if (mk != (gb & 0xFFF) &&
                __int_as_float(best[i] & 0xFFFFF000) <=
                __int_as_float(gb & 0xFFFFF000) + WMARG) {
                int pos = atomicAdd(&g_candn[rowBase + rl], 1);
                if (pos < CAP) g_candk[(rowBase + rl) * CAP + pos] = mk;
            }
        }
    }
}

// ---------------- exact fp32 fixup (warp per flagged row) ----------------
__device__ __forceinline__ float exact_score(const float* __restrict__ x,
                                             const float* __restrict__ p,
                                             int row, int k, float x2) {
    const float* xr = x + (size_t)row * DD;
    const float* pr = p + (size_t)k * DD;
    float acc = 0.f;
#pragma unroll 8
    for (int d = 0; d < DD; d++) acc = fmaf(xr[d], pr[d], acc);
    return (x2 - 2.0f * acc) + g_p2[k];
}

__global__ void fixup_kernel(const float* __restrict__ x, const float* __restrict__ p) {
    int row  = (blockIdx.x * blockDim.x + threadIdx.x) >> 5;
    int lane = threadIdx.x & 31;
    if (row >= NN) return;
    int n = g_candn[row];
    if (n == 0) return;
    float x2 = g_x2[row];
    float bv = 3.4e38f; int bi = 0x7fffffff;
    if (n > CAP) {                       // overflow: full exact scan (rare)
        for (int k = lane; k < KK; k += 32) {
            float s = exact_score(x, p, row, k, x2);
            if (s < bv || (s == bv && k < bi)) { bv = s; bi = k; }
        }
    } else {
        for (int j = lane; j < n + 1; j += 32) {
            int k = (j == n) ? g_idx[row] : g_candk[row * CAP + j];
            float s = exact_score(x, p, row, k, x2);
            if (s < bv || (s == bv && k < bi)) { bv = s; bi = k; }
        }
    }
#pragma unroll
    for (int o = 16; o > 0; o >>= 1) {
        float ov = __shfl_down_sync(0xffffffffu, bv, o);
        int   oi = __shfl_down_sync(0xffffffffu, bi, o);
        if (ov < bv || (ov == bv && oi < bi)) { bv = ov; bi = oi; }
    }
    if (lane == 0) g_idx[row] = bi;
}

// ---------------- gather ----------------
__global__ void gather_kernel(const float* __restrict__ x, const float* __restrict__ p,
                              const float* __restrict__ lab, float* __restrict__ out) {
    int row = blockIdx.x;
    int tid = threadIdx.x;
    int idx = g_idx[row];

    const float4* xr = (const float4*)(x + (size_t)row * DD);
    float4*       o0 = (float4*)(out + (size_t)row * DD);
    const float4* pr = (const float4*)(p + (size_t)idx * DD);
    float4*       o1 = (float4*)(out + (size_t)NN * DD + (size_t)row * DD);
    const float4* lr = (const float4*)(lab + (size_t)idx * CC);
    float4*       o2 = (float4*)(out + 2 * (size_t)NN * DD + (size_t)row * CC);

    if (tid < 32)       __stcs(o0 + tid,      xr[tid]);
    else if (tid < 64)  __stcs(o1 + tid - 32, pr[tid - 32]);
    for (int i = tid; i < CC / 4; i += blockDim.x) __stcs(o2 + i, lr[i]);
}

// ---------------- launch ----------------
extern "C" void kernel_launch(void* const* d_in, const int* in_sizes, int n_in,
                              void* d_out, int out_size) {
    const float* x   = (const float*)d_in[0];
    const float* p   = (const float*)d_in[1];
    const float* lab = (const float*)d_in[2];
    float* out = (float*)d_out;

    float *px2 = nullptr, *pp2 = nullptr; void* pcandn = nullptr;
    cudaGetSymbolAddress((void**)&px2, g_x2);
    cudaGetSymbolAddress((void**)&pp2, g_p2);
    cudaGetSymbolAddress(&pcandn, g_candn);

    cudaFuncSetAttribute(argmin_i8_kernel, cudaFuncAttributeMaxDynamicSharedMemorySize, SMEM_BYTES);

    cudaMemsetAsync(pcandn, 0, NN * sizeof(int));
    quant_x_kernel<<<NN * 32 / 256, 256>>>(x);
    quant_p_kernel<<<KPAD * 32 / 256, 256>>>(p);
    row_norm_kernel<<<NN / 8, 256>>>(x, px2, NN);
    row_norm_kernel<<<(KK + 7) / 8, 256>>>(p, pp2, KK);
    argmin_i8_kernel<<<NN / BM, NTHREADS, SMEM_BYTES>>>();
    fixup_kernel<<<NN * 32 / 256, 256>>>(x, p);
    gather_kernel<<<NN, 256>>>(x, p, lab, out);
}

// round 11
// speedup vs baseline: 70.1044x; 70.1044x over previous
#include <cuda_runtime.h>
#include <cstdint>

#define NN 32768
#define KK 4000
#define DD 128
#define CC 1000

#define BM 128
#define BN 128
#define NTILES 32          // 4096 padded proxies
#define KPAD (NTILES*BN)
#define TM 8
#define TN 8
#define NTHREADS 256

__device__ float g_x2[NN];
__device__ float g_p2[KPAD];
__device__ int   g_idx[NN];
__device__ __align__(16) float g_xT[DD * NN];      // x transposed [d][row], 16MB
__device__ __align__(16) float g_pT[KPAD * DD];    // proxies [tile][d][k_in_tile], 2MB

// ---------------- packed f32x2 helpers ----------------
__device__ __forceinline__ uint64_t ffma2(uint64_t a, uint64_t b, uint64_t c) {
    uint64_t d;
    asm("fma.rn.f32x2 %0, %1, %2, %3;" : "=l"(d) : "l"(a), "l"(b), "l"(c));
    return d;
}
__device__ __forceinline__ uint64_t pack2(float lo, float hi) {
    uint64_t d;
    asm("mov.b64 %0, {%1, %2};" : "=l"(d) : "f"(lo), "f"(hi));
    return d;
}
__device__ __forceinline__ float2 unpack2(uint64_t v) {
    float2 r;
    asm("mov.b64 {%0, %1}, %2;" : "=f"(r.x), "=f"(r.y) : "l"(v));
    return r;
}
__device__ __forceinline__ uint32_t smem_u32(const void* p) {
    uint32_t a;
    asm("{ .reg .u64 t; cvta.to.shared.u64 t, %1; cvt.u32.u64 %0, t; }" : "=r"(a) : "l"(p));
    return a;
}
__device__ __forceinline__ void cpa16(uint32_t dst, const void* src) {
    asm volatile("cp.async.cg.shared.global [%0], [%1], 16;" :: "r"(dst), "l"(src));
}
#define CP_COMMIT() asm volatile("cp.async.commit_group;")
#define CP_WAIT(n)  asm volatile("cp.async.wait_group %0;" :: "n"(n))

// full 64KB tile copy: 4096 x 16B chunks with 256 threads -> 16 per thread
__device__ __forceinline__ void copy_tile_64k(uint32_t dst, const char* src, int tid) {
#pragma unroll
    for (int j = 0; j < 16; j++) {
        int i = tid + NTHREADS * j;
        cpa16(dst + i * 16, src + i * 16);
    }
}

// ---------------- prep: transpose x ----------------
__global__ void prep_x_kernel(const float* __restrict__ x) {
    int c = blockIdx.x * 256 + threadIdx.x;     // NN * 32 threads
    int row = c & (NN - 1);
    int d0  = (c >> 15) << 2;
    float4 v = *(const float4*)(x + (size_t)row * DD + d0);
    g_xT[(size_t)(d0 + 0) * NN + row] = v.x;    // coalesced across consecutive rows
    g_xT[(size_t)(d0 + 1) * NN + row] = v.y;
    g_xT[(size_t)(d0 + 2) * NN + row] = v.z;
    g_xT[(size_t)(d0 + 3) * NN + row] = v.w;
}

// ---------------- prep: proxies -> transposed tiles + pad sentinels --------
__global__ void prep_p_kernel(const float* __restrict__ p) {
    int c = blockIdx.x * 256 + threadIdx.x;     // KPAD*16 chunks of 8 dims
    int k = c >> 4, d0 = (c & 15) << 3;
    float v[8];
    if (k < KK) {
        *(float4*)&v[0] = *(const float4*)(p + (size_t)k * DD + d0);
        *(float4*)&v[4] = *(const float4*)(p + (size_t)k * DD + d0 + 4);
    } else {
#pragma unroll
        for (int i = 0; i < 8; i++) v[i] = 0.f;
        if (d0 == 0) g_p2[k] = 3.0e38f;         // pad sentinel: never wins
    }
    float* base = g_pT + (size_t)(k >> 7) * (BN * DD) + (k & 127);
#pragma unroll
    for (int i = 0; i < 8; i++) base[(size_t)(d0 + i) * BN] = v[i];
}

// ---------------- row squared norms ----------------
__global__ void row_norm_kernel(const float* __restrict__ A, float* __restrict__ out, int rows) {
    int row  = blockIdx.x * 8 + (threadIdx.x >> 5);
    int lane = threadIdx.x & 31;
    if (row >= rows) return;
    const float* a = A + (size_t)row * DD;
    float s = 0.f;
#pragma unroll
    for (int i = 0; i < DD / 32; i++) { float v = a[lane + 32 * i]; s = fmaf(v, v, s); }
#pragma unroll
    for (int o = 16; o > 0; o >>= 1) s += __shfl_down_sync(0xffffffffu, s, o);
    if (lane == 0) out[row] = s;
}

// ---------------- smem layout (floats) ----------------
#define FO_A   0                       // [DD][128]
#define FO_B   (DD * 128)              // 2 x [DD][128]
#define FO_P2  (FO_B + 2 * DD * 128)   // 2 x 128
#define FO_X2  (FO_P2 + 2 * BN)        // 128
#define SMEM_FLOATS (FO_X2 + BM)
#define SMEM_BYTES  (SMEM_FLOATS * 4)  // 198,656 B

extern __shared__ float sm[];

// ---------------- fused score-GEMM + running argmin ----------------
__global__ __launch_bounds__(NTHREADS, 1)
void argmin_kernel() {
    float* As  = sm + FO_A;
    float* Bs  = sm + FO_B;
    float* p2s = sm + FO_P2;
    float* x2s = sm + FO_X2;
    uint32_t sbA = smem_u32(sm + FO_A);
    uint32_t sbB = smem_u32(sm + FO_B);

    int tid = threadIdx.x;
    int tx  = tid & 15;      // proxy group (TN=8)
    int ty  = tid >> 4;      // row group   (TM=8)
    int rowBase = blockIdx.x * BM;

    // --- prologue: A tile + B tile 0, then B tile 1 (all verbatim cp.async) ---
    {
        // A tile: strided rows from g_xT (each d-row is 128 floats = 32 chunks)
        const char* srcA0 = (const char*)(g_xT + rowBase);
#pragma unroll
        for (int j = 0; j < 16; j++) {
            int i = tid + NTHREADS * j;
            int d = i >> 5, c = i & 31;
            cpa16(sbA + (d * 128 + c * 4) * 4, srcA0 + ((size_t)d * NN + c * 4) * 4);
        }
        copy_tile_64k(sbB, (const char*)(g_pT), tid);
        if (tid < BN) p2s[tid] = g_p2[tid];
        if (tid < BM) x2s[tid] = g_x2[rowBase + tid];
        CP_COMMIT();
        copy_tile_64k(sbB + DD * 128 * 4, (const char*)(g_pT + BN * DD), tid);
        if (tid < BN) p2s[BN + tid] = g_p2[BN + tid];
        CP_COMMIT();
    }

    CP_WAIT(1);
    __syncthreads();
    float x2r[TM];
#pragma unroll
    for (int i = 0; i < TM; i++) x2r[i] = x2s[ty * TM + i];

    float bestv[TM]; int besti[TM];
#pragma unroll
    for (int i = 0; i < TM; i++) { bestv[i] = 3.0e38f; besti[i] = 0; }

    for (int t = 0; t < NTILES; t++) {
        int b = t & 1;
        if (t > 0) {
            if (t == NTILES - 1) { CP_WAIT(0); } else { CP_WAIT(1); }
            __syncthreads();
        }

        uint64_t acc[TM][TN / 2];
#pragma unroll
        for (int i = 0; i < TM; i++)
#pragma unroll
            for (int j = 0; j < TN / 2; j++) acc[i][j] = 0ull;

        const float* xb = As + ty * TM;
        const float* pb = Bs + b * (DD * 128) + tx * TN;
#pragma unroll 2
        for (int d = 0; d < DD; d++) {
            float4     xa0 = *(const float4*)(xb + d * 128);
            float4     xa1 = *(const float4*)(xb + d * 128 + 4);
            ulonglong2 pA  = *(const ulonglong2*)(pb + d * 128);
            ulonglong2 pB  = *(const ulonglong2*)(pb + d * 128 + 4);
            uint64_t xs8[TM] = { pack2(xa0.x, xa0.x), pack2(xa0.y, xa0.y),
                                 pack2(xa0.z, xa0.z), pack2(xa0.w, xa0.w),
                                 pack2(xa1.x, xa1.x), pack2(xa1.y, xa1.y),
                                 pack2(xa1.z, xa1.z), pack2(xa1.w, xa1.w) };
            uint64_t pv[TN / 2] = { pA.x, pA.y, pB.x, pB.y };
#pragma unroll
            for (int i = 0; i < TM; i++)
#pragma unroll
                for (int j = 0; j < TN / 2; j++)
                    acc[i][j] = ffma2(xs8[i], pv[j], acc[i][j]);
        }

        // running argmin (k ascending per thread; strict '<' = first-min)
        const float* pp = p2s + b * BN + tx * TN;
#pragma unroll
        for (int j = 0; j < TN / 2; j++) {
            int kg = t * BN + tx * TN + 2 * j;
            float p0 = pp[2 * j], p1 = pp[2 * j + 1];
#pragma unroll
            for (int i = 0; i < TM; i++) {
                float2 dp = unpack2(acc[i][j]);
                float s0 = (x2r[i] - 2.0f * dp.x) + p0;
                float s1 = (x2r[i] - 2.0f * dp.y) + p1;
                if (s0 < bestv[i]) { bestv[i] = s0; besti[i] = kg; }
                if (s1 < bestv[i]) { bestv[i] = s1; besti[i] = kg + 1; }
            }
        }
        __syncthreads();    // everyone done reading buffer b

        if (t + 2 < NTILES) {   // refill buffer b with tile t+2
            copy_tile_64k(sbB + b * (DD * 128 * 4),
                          (const char*)(g_pT + (size_t)(t + 2) * (BN * DD)), tid);
            if (tid < BN) p2s[b * BN + tid] = g_p2[(t + 2) * BN + tid];
            CP_COMMIT();
        }
    }

    // --- cross-thread reduction: 16 candidates per row (reuse B region) ---
    float* redv = Bs;                     // [16][BM]
    int*   redi = (int*)(Bs + 16 * BM);   // [16][BM]
#pragma unroll
    for (int i = 0; i < TM; i++) {
        int row = ty * TM + i;
        redv[tx * BM + row] = bestv[i];
        redi[tx * BM + row] = besti[i];
    }
    __syncthreads();
    if (tid < BM) {
        float bv = 3.4e38f; int bi = 0x7fffffff;
#pragma unroll
        for (int t = 0; t < 16; t++) {
            float v  = redv[t * BM + tid];
            int   ix = redi[t * BM + tid];
            if (v < bv || (v == bv && ix < bi)) { bv = v; bi = ix; }
        }
        g_idx[rowBase + tid] = bi;
    }
}

// ---------------- gather ----------------
__global__ void gather_kernel(const float* __restrict__ x, const float* __restrict__ p,
                              const float* __restrict__ lab, float* __restrict__ out) {
    int row = blockIdx.x;
    int tid = threadIdx.x;
    int idx = g_idx[row];

    const float4* xr = (const float4*)(x + (size_t)row * DD);
    float4*       o0 = (float4*)(out + (size_t)row * DD);
    const float4* pr = (const float4*)(p + (size_t)idx * DD);
    float4*       o1 = (float4*)(out + (size_t)NN * DD + (size_t)row * DD);
    const float4* lr = (const float4*)(lab + (size_t)idx * CC);
    float4*       o2 = (float4*)(out + 2 * (size_t)NN * DD + (size_t)row * CC);

    if (tid < 32)       __stcs(o0 + tid,      xr[tid]);
    else if (tid < 64)  __stcs(o1 + tid - 32, pr[tid - 32]);
    for (int i = tid; i < CC / 4; i += blockDim.x) __stcs(o2 + i, lr[i]);
}

// ---------------- launch ----------------
extern "C" void kernel_launch(void* const* d_in, const int* in_sizes, int n_in,
                              void* d_out, int out_size) {
    const float* x   = (const float*)d_in[0];
    const float* p   = (const float*)d_in[1];
    const float* lab = (const float*)d_in[2];
    float* out = (float*)d_out;

    float *px2 = nullptr, *pp2 = nullptr;
    cudaGetSymbolAddress((void**)&px2, g_x2);
    cudaGetSymbolAddress((void**)&pp2, g_p2);

    cudaFuncSetAttribute(argmin_kernel, cudaFuncAttributeMaxDynamicSharedMemorySize, SMEM_BYTES);

    row_norm_kernel<<<NN / 8, 256>>>(x, px2, NN);           // warms L2 with x
    prep_x_kernel<<<NN * 32 / 256, 256>>>(x);
    prep_p_kernel<<<KPAD * 16 / 256, 256>>>(p);
    row_norm_kernel<<<(KK + 7) / 8, 256>>>(p, pp2, KK);
    argmin_kernel<<<NN / BM, NTHREADS, SMEM_BYTES>>>();
    gather_kernel<<<NN, 256>>>(x, p, lab, out);
}

// round 13
// speedup vs baseline: 75.2609x; 1.0736x over previous
#include <cuda_runtime.h>
#include <cstdint>

#define NN 32768
#define KK 4000
#define DD 128
#define CC 1000

#define BM 128
#define BN 128
#define NTILES 32          // 4096 padded proxies
#define KPAD (NTILES*BN)
#define NSPLIT 4           // K split: 4 quarters x 8 tiles
#define TPQ (NTILES/NSPLIT)
#define TM 8
#define TN 8
#define NTHREADS 256

__device__ float g_x2[NN];
__device__ float g_p2[KPAD];
__device__ int   g_idx[NN];
__device__ __align__(16) float g_xT[DD * NN];      // x transposed [d][row], 16MB
__device__ __align__(16) float g_pT[KPAD * DD];    // proxies [tile][d][k_in_tile], 2MB
__device__ float g_partv[NSPLIT * NN];             // per-quarter best value
__device__ int   g_parti[NSPLIT * NN];             // per-quarter best index

// ---------------- packed f32x2 helpers ----------------
__device__ __forceinline__ uint64_t ffma2(uint64_t a, uint64_t b, uint64_t c) {
    uint64_t d;
    asm("fma.rn.f32x2 %0, %1, %2, %3;" : "=l"(d) : "l"(a), "l"(b), "l"(c));
    return d;
}
__device__ __forceinline__ uint64_t pack2(float lo, float hi) {
    uint64_t d;
    asm("mov.b64 %0, {%1, %2};" : "=l"(d) : "f"(lo), "f"(hi));
    return d;
}
__device__ __forceinline__ float2 unpack2(uint64_t v) {
    float2 r;
    asm("mov.b64 {%0, %1}, %2;" : "=f"(r.x), "=f"(r.y) : "l"(v));
    return r;
}
__device__ __forceinline__ uint32_t smem_u32(const void* p) {
    uint32_t a;
    asm("{ .reg .u64 t; cvta.to.shared.u64 t, %1; cvt.u32.u64 %0, t; }" : "=r"(a) : "l"(p));
    return a;
}
__device__ __forceinline__ void cpa16(uint32_t dst, const void* src) {
    asm volatile("cp.async.cg.shared.global [%0], [%1], 16;" :: "r"(dst), "l"(src));
}
#define CP_COMMIT() asm volatile("cp.async.commit_group;")
#define CP_WAIT(n)  asm volatile("cp.async.wait_group %0;" :: "n"(n))

// full 64KB tile copy: 4096 x 16B chunks with 256 threads -> 16 per thread
__device__ __forceinline__ void copy_tile_64k(uint32_t dst, const char* src, int tid) {
#pragma unroll
    for (int j = 0; j < 16; j++) {
        int i = tid + NTHREADS * j;
        cpa16(dst + i * 16, src + i * 16);
    }
}

// ---------------- prep: transpose x ----------------
__global__ void prep_x_kernel(const float* __restrict__ x) {
    int c = blockIdx.x * 256 + threadIdx.x;     // NN * 32 threads
    int row = c & (NN - 1);
    int d0  = (c >> 15) << 2;
    float4 v = *(const float4*)(x + (size_t)row * DD + d0);
    g_xT[(size_t)(d0 + 0) * NN + row] = v.x;
    g_xT[(size_t)(d0 + 1) * NN + row] = v.y;
    g_xT[(size_t)(d0 + 2) * NN + row] = v.z;
    g_xT[(size_t)(d0 + 3) * NN + row] = v.w;
}

// ---------------- prep: proxies -> transposed tiles + pad sentinels --------
__global__ void prep_p_kernel(const float* __restrict__ p) {
    int c = blockIdx.x * 256 + threadIdx.x;     // KPAD*16 chunks of 8 dims
    int k = c >> 4, d0 = (c & 15) << 3;
    float v[8];
    if (k < KK) {
        *(float4*)&v[0] = *(const float4*)(p + (size_t)k * DD + d0);
        *(float4*)&v[4] = *(const float4*)(p + (size_t)k * DD + d0 + 4);
    } else {
#pragma unroll
        for (int i = 0; i < 8; i++) v[i] = 0.f;
        if (d0 == 0) g_p2[k] = 3.0e38f;         // pad sentinel: never wins
    }
    float* base = g_pT + (size_t)(k >> 7) * (BN * DD) + (k & 127);
#pragma unroll
    for (int i = 0; i < 8; i++) base[(size_t)(d0 + i) * BN] = v[i];
}

// ---------------- row squared norms ----------------
__global__ void row_norm_kernel(const float* __restrict__ A, float* __restrict__ out, int rows) {
    int row  = blockIdx.x * 8 + (threadIdx.x >> 5);
    int lane = threadIdx.x & 31;
    if (row >= rows) return;
    const float* a = A + (size_t)row * DD;
    float s = 0.f;
#pragma unroll
    for (int i = 0; i < DD / 32; i++) { float v = a[lane + 32 * i]; s = fmaf(v, v, s); }
#pragma unroll
    for (int o = 16; o > 0; o >>= 1) s += __shfl_down_sync(0xffffffffu, s, o);
    if (lane == 0) out[row] = s;
}

// ---------------- smem layout (floats) ----------------
#define FO_A   0                       // [DD][128]
#define FO_B   (DD * 128)              // 2 x [DD][128]
#define FO_P2  (FO_B + 2 * DD * 128)   // 2 x 128
#define FO_X2  (FO_P2 + 2 * BN)        // 128
#define SMEM_FLOATS (FO_X2 + BM)
#define SMEM_BYTES  (SMEM_FLOATS * 4)  // 198,656 B

extern __shared__ float sm[];

// ---------------- fused score-GEMM + running argmin (one K quarter) ---------
__global__ __launch_bounds__(NTHREADS, 1)
void argmin_kernel() {
    float* As  = sm + FO_A;
    float* Bs  = sm + FO_B;
    float* p2s = sm + FO_P2;
    float* x2s = sm + FO_X2;
    uint32_t sbA = smem_u32(sm + FO_A);
    uint32_t sbB = smem_u32(sm + FO_B);

    int tid = threadIdx.x;
    int tx  = tid & 15;      // proxy group (TN=8)
    int ty  = tid >> 4;      // row group   (TM=8)
    int rowBase = blockIdx.x * BM;
    int q       = blockIdx.y;            // K quarter
    int t0      = q * TPQ;               // first tile of this quarter

    // --- prologue: A tile + B tiles t0, t0+1 (all verbatim cp.async) ---
    {
        const char* srcA0 = (const char*)(g_xT + rowBase);
#pragma unroll
        for (int j = 0; j < 16; j++) {
            int i = tid + NTHREADS * j;
            int d = i >> 5, c = i & 31;
            cpa16(sbA + (d * 128 + c * 4) * 4, srcA0 + ((size_t)d * NN + c * 4) * 4);
        }
        copy_tile_64k(sbB, (const char*)(g_pT + (size_t)t0 * (BN * DD)), tid);
        if (tid < BN) p2s[tid] = g_p2[t0 * BN + tid];
        if (tid < BM) x2s[tid] = g_x2[rowBase + tid];
        CP_COMMIT();
        copy_tile_64k(sbB + DD * 128 * 4, (const char*)(g_pT + (size_t)(t0 + 1) * (BN * DD)), tid);
        if (tid < BN) p2s[BN + tid] = g_p2[(t0 + 1) * BN + tid];
        CP_COMMIT();
    }

    CP_WAIT(1);
    __syncthreads();
    float x2r[TM];
#pragma unroll
    for (int i = 0; i < TM; i++) x2r[i] = x2s[ty * TM + i];

    float bestv[TM]; int besti[TM];
#pragma unroll
    for (int i = 0; i < TM; i++) { bestv[i] = 3.0e38f; besti[i] = 0; }

    for (int tl = 0; tl < TPQ; tl++) {
        int t = t0 + tl;
        int b = tl & 1;
        if (tl > 0) {
            if (tl == TPQ - 1) { CP_WAIT(0); } else { CP_WAIT(1); }
            __syncthreads();
        }

        uint64_t acc[TM][TN / 2];
#pragma unroll
        for (int i = 0; i < TM; i++)
#pragma unroll
            for (int j = 0; j < TN / 2; j++) acc[i][j] = 0ull;

        const float* xb = As + ty * TM;
        const float* pb = Bs + b * (DD * 128) + tx * TN;
#pragma unroll 2
        for (int d = 0; d < DD; d++) {
            float4     xa0 = *(const float4*)(xb + d * 128);
            float4     xa1 = *(const float4*)(xb + d * 128 + 4);
            ulonglong2 pA  = *(const ulonglong2*)(pb + d * 128);
            ulonglong2 pB  = *(const ulonglong2*)(pb + d * 128 + 4);
            uint64_t xs8[TM] = { pack2(xa0.x, xa0.x), pack2(xa0.y, xa0.y),
                                 pack2(xa0.z, xa0.z), pack2(xa0.w, xa0.w),
                                 pack2(xa1.x, xa1.x), pack2(xa1.y, xa1.y),
                                 pack2(xa1.z, xa1.z), pack2(xa1.w, xa1.w) };
            uint64_t pv[TN / 2] = { pA.x, pA.y, pB.x, pB.y };
#pragma unroll
            for (int i = 0; i < TM; i++)
#pragma unroll
                for (int j = 0; j < TN / 2; j++)
                    acc[i][j] = ffma2(xs8[i], pv[j], acc[i][j]);
        }

        // running argmin (k ascending per thread; strict '<' = first-min)
        const float* pp = p2s + b * BN + tx * TN;
#pragma unroll
        for (int j = 0; j < TN / 2; j++) {
            int kg = t * BN + tx * TN + 2 * j;
            float p0 = pp[2 * j], p1 = pp[2 * j + 1];
#pragma unroll
            for (int i = 0; i < TM; i++) {
                float2 dp = unpack2(acc[i][j]);
                float s0 = (x2r[i] - 2.0f * dp.x) + p0;
                float s1 = (x2r[i] - 2.0f * dp.y) + p1;
                if (s0 < bestv[i]) { bestv[i] = s0; besti[i] = kg; }
                if (s1 < bestv[i]) { bestv[i] = s1; besti[i] = kg + 1; }
            }
        }
        __syncthreads();    // everyone done reading buffer b

        if (tl + 2 < TPQ) {   // refill buffer b with tile t+2
            copy_tile_64k(sbB + b * (DD * 128 * 4),
                          (const char*)(g_pT + (size_t)(t + 2) * (BN * DD)), tid);
            if (tid < BN) p2s[b * BN + tid] = g_p2[(t + 2) * BN + tid];
            CP_COMMIT();
        }
    }

    // --- cross-thread reduction: 16 candidates per row (reuse B region) ---
    float* redv = Bs;                     // [16][BM]
    int*   redi = (int*)(Bs + 16 * BM);   // [16][BM]
#pragma unroll
    for (int i = 0; i < TM; i++) {
        int row = ty * TM + i;
        redv[tx * BM + row] = bestv[i];
        redi[tx * BM + row] = besti[i];
    }
    __syncthreads();
    if (tid < BM) {
        float bv = 3.4e38f; int bi = 0x7fffffff;
#pragma unroll
        for (int t = 0; t < 16; t++) {
            float v  = redv[t * BM + tid];
            int   ix = redi[t * BM + tid];
            if (v < bv || (v == bv && ix < bi)) { bv = v; bi = ix; }
        }
        g_partv[q * NN + rowBase + tid] = bv;
        g_parti[q * NN + rowBase + tid] = bi;
    }
}

// ---------------- merge quarters (k-ascending, strict '<' keeps lowest k) ----
__global__ void merge_kernel() {
    int row = blockIdx.x * 256 + threadIdx.x;
    float bv = g_partv[row];
    int   bi = g_parti[row];
#pragma unroll
    for (int qq = 1; qq < NSPLIT; qq++) {
        float v  = g_partv[qq * NN + row];
        int   ix = g_parti[qq * NN + row];
        if (v < bv) { bv = v; bi = ix; }   // quarters disjoint ascending: tie keeps earlier
    }
    g_idx[row] = bi;
}

// ---------------- gather ----------------
__global__ void gather_kernel(const float* __restrict__ x, const float* __restrict__ p,
                              const float* __restrict__ lab, float* __restrict__ out) {
    int row = blockIdx.x;
    int tid = threadIdx.x;
    int idx = g_idx[row];

    const float4* xr = (const float4*)(x + (size_t)row * DD);
    float4*       o0 = (float4*)(out + (size_t)row * DD);
    const float4* pr = (const float4*)(p + (size_t)idx * DD);
    float4*       o1 = (float4*)(out + (size_t)NN * DD + (size_t)row * DD);
    const float4* lr = (const float4*)(lab + (size_t)idx * CC);
    float4*       o2 = (float4*)(out + 2 * (size_t)NN * DD + (size_t)row * CC);

    if (tid < 32)       __stcs(o0 + tid,      xr[tid]);
    else if (tid < 64)  __stcs(o1 + tid - 32, pr[tid - 32]);
    for (int i = tid; i < CC / 4; i += blockDim.x) __stcs(o2 + i, lr[i]);
}

// ---------------- launch ----------------
extern "C" void kernel_launch(void* const* d_in, const int* in_sizes, int n_in,
                              void* d_out, int out_size) {
    const float* x   = (const float*)d_in[0];
    const float* p   = (const float*)d_in[1];
    const float* lab = (const float*)d_in[2];
    float* out = (float*)d_out;

    float *px2 = nullptr, *pp2 = nullptr;
    cudaGetSymbolAddress((void**)&px2, g_x2);
    cudaGetSymbolAddress((void**)&pp2, g_p2);

    cudaFuncSetAttribute(argmin_kernel, cudaFuncAttributeMaxDynamicSharedMemorySize, SMEM_BYTES);

    row_norm_kernel<<<NN / 8, 256>>>(x, px2, NN);           // warms L2 with x
    prep_x_kernel<<<NN * 32 / 256, 256>>>(x);
    prep_p_kernel<<<KPAD * 16 / 256, 256>>>(p);
    row_norm_kernel<<<(KK + 7) / 8, 256>>>(p, pp2, KK);
    argmin_kernel<<<dim3(NN / BM, NSPLIT), NTHREADS, SMEM_BYTES>>>();
    merge_kernel<<<NN / 256, 256>>>();
    gather_kernel<<<NN, 256>>>(x, p, lab, out);
}